// round 4
// baseline (speedup 1.0000x reference)
#include <cuda_runtime.h>
#include <cstdint>
#include <cstddef>

// Problem constants (fixed by the reference)
#define BB    4
#define NN    4096
#define FIN   256
#define FOUT  64
#define ALPHA 0.2f

#define TM    128             // rows per attention block
#define TJ    64              // j per tile
#define NT    (NN / TJ)       // 64 tiles

using u64 = unsigned long long;

// Scratch (device globals: no allocation allowed)
__device__ float g_Wh [BB * NN * FOUT];   // 4 MB
__device__ float g_Wh1[BB * NN];
__device__ float g_Wh2[BB * NN];
__device__ float g_max2[BB];
__device__ float g_eA[BB * NN];           // exp(w1 - m_i)
__device__ float g_eC[BB * NN];           // exp(a*w1 - m_i)
__device__ float g_eB[BB * NN];           // exp(w2)
__device__ float g_eD[BB * NN];           // exp(a*w2)

// ---------- packed f32x2 helpers ----------
__device__ __forceinline__ u64 pk2(float lo, float hi) {
    u64 r; asm("mov.b64 %0, {%1, %2};" : "=l"(r) : "f"(lo), "f"(hi)); return r;
}
__device__ __forceinline__ u64 fma2(u64 a, u64 b, u64 c) {
    u64 d; asm("fma.rn.f32x2 %0, %1, %2, %3;" : "=l"(d) : "l"(a), "l"(b), "l"(c)); return d;
}
__device__ __forceinline__ float2 upk2(u64 v) {
    float2 r; asm("mov.b64 {%0, %1}, %2;" : "=f"(r.x), "=f"(r.y) : "l"(v)); return r;
}

// Order-independent (deterministic) float atomic max.
__device__ __forceinline__ void atomicMaxFloat(float* addr, float v) {
    if (v >= 0.f) atomicMax((int*)addr,          __float_as_int(v));
    else          atomicMin((unsigned int*)addr, __float_as_uint(v));
}

// ---------------------------------------------------------------------------
// K_init: reset per-batch max accumulators.
// ---------------------------------------------------------------------------
__global__ void k_init() {
    if (threadIdx.x < BB) g_max2[threadIdx.x] = -3.0e38f;
}

// ---------------------------------------------------------------------------
// K_proj: tiled GEMM  Wh = h @ W + bias, fused Wh1/Wh2 dots and per-batch
// running max of Wh2 (deterministic atomicMax). 256 thr, 64 rows/block.
// ---------------------------------------------------------------------------
__global__ void __launch_bounds__(256, 2)
k_proj(const float* __restrict__ h, const float* __restrict__ W,
       const float* __restrict__ a, const float* __restrict__ bias) {
    __shared__ __align__(16) float sH[64 * 68];
    __shared__ __align__(16) float sW[64 * 64];

    int tid = threadIdx.x;
    int ti = tid >> 4;
    int jq = tid & 15;
    int i0 = blockIdx.x * 64;

    u64 acc[4][2];
#pragma unroll
    for (int r = 0; r < 4; r++) { acc[r][0] = 0ull; acc[r][1] = 0ull; }

    for (int kc = 0; kc < 4; kc++) {
        int k0 = kc * 64;
#pragma unroll
        for (int u = 0; u < 4; u++) {
            int q = tid + u * 256;
            int row = q >> 4, c4 = q & 15;
            *(float4*)(sH + row * 68 + c4 * 4) =
                *(const float4*)(h + (size_t)(i0 + row) * FIN + k0 + c4 * 4);
            *(float4*)(sW + row * 64 + c4 * 4) =
                *(const float4*)(W + (size_t)(k0 + row) * FOUT + c4 * 4);
        }
        __syncthreads();

#pragma unroll 4
        for (int k = 0; k < 64; k++) {
            ulonglong2 wv = *(const ulonglong2*)(sW + k * 64 + 4 * jq);
#pragma unroll
            for (int r = 0; r < 4; r++) {
                float hv = sH[(ti * 4 + r) * 68 + k];
                u64 hh = pk2(hv, hv);
                acc[r][0] = fma2(hh, wv.x, acc[r][0]);
                acc[r][1] = fma2(hh, wv.y, acc[r][1]);
            }
        }
        __syncthreads();
    }

    float4 bv = *(const float4*)(bias + 4 * jq);
    float4 a1 = *(const float4*)(a + 4 * jq);
    float4 a2 = *(const float4*)(a + FOUT + 4 * jq);
    float p1[4], p2[4];
#pragma unroll
    for (int r = 0; r < 4; r++) {
        float2 v01 = upk2(acc[r][0]), v23 = upk2(acc[r][1]);
        float4 wh = make_float4(v01.x + bv.x, v01.y + bv.y,
                                v23.x + bv.z, v23.y + bv.w);
        int grow = i0 + ti * 4 + r;
        *(float4*)(g_Wh + (size_t)grow * FOUT + 4 * jq) = wh;
        p1[r] = wh.x * a1.x + wh.y * a1.y + wh.z * a1.z + wh.w * a1.w;
        p2[r] = wh.x * a2.x + wh.y * a2.y + wh.z * a2.z + wh.w * a2.w;
    }

    float* sR1 = sH;
    float* sR2 = sH + 1024;
#pragma unroll
    for (int r = 0; r < 4; r++) {
        sR1[jq * 64 + ti * 4 + r] = p1[r];
        sR2[jq * 64 + ti * 4 + r] = p2[r];
    }
    __syncthreads();
    if (tid < 64) {
        float w1 = 0.f, w2 = 0.f;
#pragma unroll
        for (int q = 0; q < 16; q++) {
            w1 += sR1[q * 64 + tid];
            w2 += sR2[q * 64 + tid];
        }
        g_Wh1[i0 + tid] = w1;
        g_Wh2[i0 + tid] = w2;
        float m = w2;
#pragma unroll
        for (int o = 16; o > 0; o >>= 1)
            m = fmaxf(m, __shfl_xor_sync(0xFFFFFFFFu, m, o));
        if ((tid & 31) == 0) atomicMaxFloat(&g_max2[i0 >> 12], m);
    }
}

// ---------------------------------------------------------------------------
// K_prep: factor the attention exponential into per-row/per-col arrays.
//   e_ij - m_i = lrelu(w1_i + w2_j) - m_i
//   exp(.) = max( e^{w1-m} * e^{w2},  e^{a*w1-m} * e^{a*w2} )
// (max picks the correct LeakyReLU branch by monotonicity of exp)
// ---------------------------------------------------------------------------
__global__ void k_prep() {
    int idx = blockIdx.x * blockDim.x + threadIdx.x;
    if (idx >= BB * NN) return;
    int b = idx >> 12;
    float mx = g_max2[b];
    float w1 = g_Wh1[idx];
    float w2 = g_Wh2[idx];
    float e = w1 + mx;
    float m = fmaxf(e, ALPHA * e);        // m_i >= all e_ij (upper bound)
    g_eA[idx] = __expf(w1 - m);
    g_eC[idx] = __expf(ALPHA * w1 - m);
    g_eB[idx] = __expf(w2);
    g_eD[idx] = __expf(ALPHA * w2);
}

// k_attn smem layout (dynamic)
#define SM_P   0u        // P dup-pairs: 64 j x 128 rows x 8B = 64 KB (swizzled)
#define SM_W   65536u    // W tile: 64 j x 64 f x 4B = 16 KB
#define SM_LP  81920u    // lsum partials [16][128] = 8 KB
#define SM_L   90112u    // row sums [128] (+pad)
#define SMEM_ATTN 90624u

// ---------------------------------------------------------------------------
// K_attn: fused masked-softmax attention + PV + ELU. 512 thr, TM=128 rows.
// Thread (rg = tid>>4: rows rg*4..+3, q = tid&15: phase1 j-quad / phase2 feat-quad).
// P stored as duplicated (p,p) pairs, 16B units swizzled by c(j)=(j>>2)&7 so
// phase-1 stores are conflict-free and phase-2 reads are pure broadcast.
// ---------------------------------------------------------------------------
__global__ void __launch_bounds__(512, 1)
k_attn(const int* __restrict__ adj, float* __restrict__ out) {
    extern __shared__ __align__(16) unsigned char smem[];
    float* sW = (float*)(smem + SM_W);

    int tid = threadIdx.x;
    int b  = blockIdx.x >> 5;                 // 32 blocks per batch
    int i0 = (blockIdx.x & 31) * TM;
    int rg = tid >> 4;                        // 0..31
    int q  = tid & 15;                        // 0..15
    int r0 = rg * 4;

    // Per-row constants
    float eA[4], eC[4], lsum[4];
#pragma unroll
    for (int r = 0; r < 4; r++) {
        int gi = b * NN + i0 + r0 + r;
        eA[r] = g_eA[gi];
        eC[r] = g_eC[gi];
        lsum[r] = 0.f;
    }

    u64 acc[4][2];
#pragma unroll
    for (int r = 0; r < 4; r++) { acc[r][0] = 0ull; acc[r][1] = 0ull; }

    const int*   adjp = adj + (size_t)(b * NN + i0 + r0) * NN + 4 * q;
    const float* eBp  = g_eB + b * NN + 4 * q;
    const float* eDp  = g_eD + b * NN + 4 * q;
    const float* gW   = g_Wh + (size_t)b * NN * FOUT;

    // Prefetch tile 0: adjacency (4 int4) + W (2 float4)
    int4 av[4];
#pragma unroll
    for (int r = 0; r < 4; r++) av[r] = *(const int4*)(adjp + (size_t)r * NN);
    float4 wA = *(const float4*)(gW + tid * 8);
    float4 wB = *(const float4*)(gW + tid * 8 + 4);

    for (int t = 0; t < NT; t++) {
        int j0 = t * TJ;

        // Per-j factor vectors for this thread's 4 j's
        float4 vB = *(const float4*)(eBp + j0);
        float4 vD = *(const float4*)(eDp + j0);

        // Phase 1: P[jj][r] = adj ? max(eA_r*B_j, eC_r*D_j) : 0
        float p[4][4];
#pragma unroll
        for (int r = 0; r < 4; r++) {
            int4 a4 = av[r];
            float v;
            v = fmaxf(eA[r] * vB.x, eC[r] * vD.x); p[0][r] = (a4.x > 0) ? v : 0.f;
            v = fmaxf(eA[r] * vB.y, eC[r] * vD.y); p[1][r] = (a4.y > 0) ? v : 0.f;
            v = fmaxf(eA[r] * vB.z, eC[r] * vD.z); p[2][r] = (a4.z > 0) ? v : 0.f;
            v = fmaxf(eA[r] * vB.w, eC[r] * vD.w); p[3][r] = (a4.w > 0) ? v : 0.f;
            lsum[r] += (p[0][r] + p[1][r]) + (p[2][r] + p[3][r]);
        }
        // Swizzled duplicated-pair stores
#pragma unroll
        for (int jj = 0; jj < 4; jj++) {
            unsigned j = (unsigned)(q * 4 + jj);
            unsigned c = (j >> 2) & 7u;
            unsigned base = SM_P + j * 1024u;
            *(float4*)(smem + base + ((((unsigned)(rg * 2)    ) ^ c) << 4)) =
                make_float4(p[jj][0], p[jj][0], p[jj][1], p[jj][1]);
            *(float4*)(smem + base + ((((unsigned)(rg * 2 + 1)) ^ c) << 4)) =
                make_float4(p[jj][2], p[jj][2], p[jj][3], p[jj][3]);
        }
        // Stage W tile
        *(float4*)(sW + tid * 8)     = wA;
        *(float4*)(sW + tid * 8 + 4) = wB;

        // Prefetch tile t+1 (overlaps phase 2)
        if (t + 1 < NT) {
#pragma unroll
            for (int r = 0; r < 4; r++)
                av[r] = *(const int4*)(adjp + (size_t)r * NN + j0 + TJ);
            wA = *(const float4*)(gW + (size_t)(j0 + TJ) * FOUT + tid * 8);
            wB = *(const float4*)(gW + (size_t)(j0 + TJ) * FOUT + tid * 8 + 4);
        }
        __syncthreads();

        // Phase 2: O[4x4] += P[4xTJ] @ Wh[TJx4] (packed f32x2 FMA)
#pragma unroll 4
        for (int j = 0; j < TJ; j++) {
            unsigned c = ((unsigned)j >> 2) & 7u;
            const unsigned char* pb = smem + SM_P + (unsigned)j * 1024u;
            ulonglong2 P01 = *(const ulonglong2*)(pb + ((((unsigned)(rg * 2)    ) ^ c) << 4));
            ulonglong2 P23 = *(const ulonglong2*)(pb + ((((unsigned)(rg * 2 + 1)) ^ c) << 4));
            ulonglong2 wv  = *(const ulonglong2*)(sW + j * 64 + q * 4);
            acc[0][0] = fma2(P01.x, wv.x, acc[0][0]);
            acc[0][1] = fma2(P01.x, wv.y, acc[0][1]);
            acc[1][0] = fma2(P01.y, wv.x, acc[1][0]);
            acc[1][1] = fma2(P01.y, wv.y, acc[1][1]);
            acc[2][0] = fma2(P23.x, wv.x, acc[2][0]);
            acc[2][1] = fma2(P23.x, wv.y, acc[2][1]);
            acc[3][0] = fma2(P23.y, wv.x, acc[3][0]);
            acc[3][1] = fma2(P23.y, wv.y, acc[3][1]);
        }
        __syncthreads();
    }

    // Deterministic lsum reduction across the 16 q partials
    float* sLp = (float*)(smem + SM_LP);
    float* sL  = (float*)(smem + SM_L);
#pragma unroll
    for (int r = 0; r < 4; r++) sLp[q * 128 + r0 + r] = lsum[r];
    __syncthreads();
    if (tid < 128) {
        float s = 0.f;
#pragma unroll
        for (int u = 0; u < 16; u++) s += sLp[u * 128 + tid];
        sL[tid] = s;
    }
    __syncthreads();

    // Epilogue: softmax divide, ELU, store
#pragma unroll
    for (int r = 0; r < 4; r++) {
        float inv = 1.0f / sL[r0 + r];
        float2 v01 = upk2(acc[r][0]);
        float2 v23 = upk2(acc[r][1]);
        float x0 = v01.x * inv, x1 = v01.y * inv;
        float x2 = v23.x * inv, x3 = v23.y * inv;
        float4 o;
        o.x = (x0 > 0.f) ? x0 : expm1f(x0);
        o.y = (x1 > 0.f) ? x1 : expm1f(x1);
        o.z = (x2 > 0.f) ? x2 : expm1f(x2);
        o.w = (x3 > 0.f) ? x3 : expm1f(x3);
        *(float4*)(out + (size_t)(b * NN + i0 + r0 + r) * FOUT + 4 * q) = o;
    }
}

// ---------------------------------------------------------------------------
// Inputs (metadata order): h[f32], adj[i32], W[f32], a[f32], bias[f32]
// ---------------------------------------------------------------------------
extern "C" void kernel_launch(void* const* d_in, const int* in_sizes, int n_in,
                              void* d_out, int out_size) {
    const float* h    = (const float*)d_in[0];
    const int*   adj  = (const int*)  d_in[1];
    const float* W    = (const float*)d_in[2];
    const float* a    = (const float*)d_in[3];
    const float* bias = (const float*)d_in[4];
    float* out = (float*)d_out;

    cudaFuncSetAttribute(k_attn, cudaFuncAttributeMaxDynamicSharedMemorySize,
                         (int)SMEM_ATTN);

    k_init<<<1, 32>>>();
    k_proj<<<(BB * NN) / 64, 256>>>(h, W, a, bias);
    k_prep<<<(BB * NN) / 256, 256>>>();
    k_attn<<<BB * (NN / TM), 512, SMEM_ATTN>>>(adj, out);
}

// round 5
// speedup vs baseline: 1.3155x; 1.3155x over previous
#include <cuda_runtime.h>
#include <cstdint>
#include <cstddef>

// Problem constants (fixed by the reference)
#define BB    4
#define NN    4096
#define FIN   256
#define FOUT  64
#define ALPHA 0.2f

#define TMR   64              // rows per attention CTA
#define TJ    64              // j per tile
#define NT    (NN / TJ)       // 64 tiles

using u64 = unsigned long long;

// Scratch (device globals: no allocation allowed)
__device__ float g_Wh [BB * NN * FOUT];   // 4 MB
__device__ float g_Wh1[BB * NN];
__device__ float g_Wh2[BB * NN];
__device__ float g_max2[BB];
__device__ float g_eA[BB * NN];           // exp(w1 - m_i)
__device__ float g_eC[BB * NN];           // exp(a*w1 - m_i)
__device__ float g_eB[BB * NN];           // exp(w2)
__device__ float g_eD[BB * NN];           // exp(a*w2)

// ---------- packed f32x2 helpers (used by k_proj) ----------
__device__ __forceinline__ u64 pk2(float lo, float hi) {
    u64 r; asm("mov.b64 %0, {%1, %2};" : "=l"(r) : "f"(lo), "f"(hi)); return r;
}
__device__ __forceinline__ u64 fma2(u64 a, u64 b, u64 c) {
    u64 d; asm("fma.rn.f32x2 %0, %1, %2, %3;" : "=l"(d) : "l"(a), "l"(b), "l"(c)); return d;
}
__device__ __forceinline__ float2 upk2(u64 v) {
    float2 r; asm("mov.b64 {%0, %1}, %2;" : "=f"(r.x), "=f"(r.y) : "l"(v)); return r;
}

// ---------- TF32 MMA helpers (baseline sm_80+ ISA, compiles at compute_100) ----------
__device__ __forceinline__ uint32_t tf32_of(float f) {
    uint32_t r; asm("cvt.rna.tf32.f32 %0, %1;" : "=r"(r) : "f"(f)); return r;
}
__device__ __forceinline__ void mma_tf32(float& d0, float& d1, float& d2, float& d3,
                                         uint32_t a0, uint32_t a1, uint32_t a2, uint32_t a3,
                                         uint32_t b0, uint32_t b1) {
    asm volatile(
        "mma.sync.aligned.m16n8k8.row.col.f32.tf32.tf32.f32 "
        "{%0,%1,%2,%3}, {%4,%5,%6,%7}, {%8,%9}, {%0,%1,%2,%3};"
        : "+f"(d0), "+f"(d1), "+f"(d2), "+f"(d3)
        : "r"(a0), "r"(a1), "r"(a2), "r"(a3), "r"(b0), "r"(b1));
}

// Order-independent (deterministic) float atomic max.
__device__ __forceinline__ void atomicMaxFloat(float* addr, float v) {
    if (v >= 0.f) atomicMax((int*)addr,          __float_as_int(v));
    else          atomicMin((unsigned int*)addr, __float_as_uint(v));
}

// ---------------------------------------------------------------------------
// K_init: reset per-batch max accumulators.
// ---------------------------------------------------------------------------
__global__ void k_init() {
    if (threadIdx.x < BB) g_max2[threadIdx.x] = -3.0e38f;
}

// ---------------------------------------------------------------------------
// K_proj: tiled GEMM  Wh = h @ W + bias, fused Wh1/Wh2 dots and per-batch
// running max of Wh2 (deterministic atomicMax). 256 thr, 64 rows/block.
// ---------------------------------------------------------------------------
__global__ void __launch_bounds__(256, 2)
k_proj(const float* __restrict__ h, const float* __restrict__ W,
       const float* __restrict__ a, const float* __restrict__ bias) {
    __shared__ __align__(16) float sH[64 * 68];
    __shared__ __align__(16) float sW[64 * 64];

    int tid = threadIdx.x;
    int ti = tid >> 4;
    int jq = tid & 15;
    int i0 = blockIdx.x * 64;

    u64 acc[4][2];
#pragma unroll
    for (int r = 0; r < 4; r++) { acc[r][0] = 0ull; acc[r][1] = 0ull; }

    for (int kc = 0; kc < 4; kc++) {
        int k0 = kc * 64;
#pragma unroll
        for (int u = 0; u < 4; u++) {
            int q = tid + u * 256;
            int row = q >> 4, c4 = q & 15;
            *(float4*)(sH + row * 68 + c4 * 4) =
                *(const float4*)(h + (size_t)(i0 + row) * FIN + k0 + c4 * 4);
            *(float4*)(sW + row * 64 + c4 * 4) =
                *(const float4*)(W + (size_t)(k0 + row) * FOUT + c4 * 4);
        }
        __syncthreads();

#pragma unroll 4
        for (int k = 0; k < 64; k++) {
            ulonglong2 wv = *(const ulonglong2*)(sW + k * 64 + 4 * jq);
#pragma unroll
            for (int r = 0; r < 4; r++) {
                float hv = sH[(ti * 4 + r) * 68 + k];
                u64 hh = pk2(hv, hv);
                acc[r][0] = fma2(hh, wv.x, acc[r][0]);
                acc[r][1] = fma2(hh, wv.y, acc[r][1]);
            }
        }
        __syncthreads();
    }

    float4 bv = *(const float4*)(bias + 4 * jq);
    float4 a1 = *(const float4*)(a + 4 * jq);
    float4 a2 = *(const float4*)(a + FOUT + 4 * jq);
    float p1[4], p2[4];
#pragma unroll
    for (int r = 0; r < 4; r++) {
        float2 v01 = upk2(acc[r][0]), v23 = upk2(acc[r][1]);
        float4 wh = make_float4(v01.x + bv.x, v01.y + bv.y,
                                v23.x + bv.z, v23.y + bv.w);
        int grow = i0 + ti * 4 + r;
        *(float4*)(g_Wh + (size_t)grow * FOUT + 4 * jq) = wh;
        p1[r] = wh.x * a1.x + wh.y * a1.y + wh.z * a1.z + wh.w * a1.w;
        p2[r] = wh.x * a2.x + wh.y * a2.y + wh.z * a2.z + wh.w * a2.w;
    }

    float* sR1 = sH;
    float* sR2 = sH + 1024;
#pragma unroll
    for (int r = 0; r < 4; r++) {
        sR1[jq * 64 + ti * 4 + r] = p1[r];
        sR2[jq * 64 + ti * 4 + r] = p2[r];
    }
    __syncthreads();
    if (tid < 64) {
        float w1 = 0.f, w2 = 0.f;
#pragma unroll
        for (int q = 0; q < 16; q++) {
            w1 += sR1[q * 64 + tid];
            w2 += sR2[q * 64 + tid];
        }
        g_Wh1[i0 + tid] = w1;
        g_Wh2[i0 + tid] = w2;
        float m = w2;
#pragma unroll
        for (int o = 16; o > 0; o >>= 1)
            m = fmaxf(m, __shfl_xor_sync(0xFFFFFFFFu, m, o));
        if ((tid & 31) == 0) atomicMaxFloat(&g_max2[i0 >> 12], m);
    }
}

// ---------------------------------------------------------------------------
// K_prep: factor the attention exponential:
//   exp(lrelu(w1_i + w2_j) - m_i) = max(e^{w1-m} e^{w2}, e^{a w1 - m} e^{a w2})
// ---------------------------------------------------------------------------
__global__ void k_prep() {
    int idx = blockIdx.x * blockDim.x + threadIdx.x;
    if (idx >= BB * NN) return;
    int b = idx >> 12;
    float mx = g_max2[b];
    float w1 = g_Wh1[idx];
    float w2 = g_Wh2[idx];
    float e = w1 + mx;
    float m = fmaxf(e, ALPHA * e);        // m_i >= all e_ij
    g_eA[idx] = __expf(w1 - m);
    g_eC[idx] = __expf(ALPHA * w1 - m);
    g_eB[idx] = __expf(w2);
    g_eD[idx] = __expf(ALPHA * w2);
}

// ---------------------------------------------------------------------------
// K_attn: fused masked-softmax attention; PV product on mma.sync m16n8k8 TF32.
//
// CTA: 64 rows, 256 threads = 8 warps: warp w -> row band (w>>1)*16, feat half
// (w&1)*32. A-fragments (P) are BUILT IN REGISTERS per the HW fragment layout
// (P never touches smem). B (= Wh tile, TF32 hi+lo split) is staged in smem
// [f][k] with stride 68 (bank = 4n+c -> conflict-free fragment loads).
// j-permutation pi: logical j = 2c -> MMA k=c, j = 2c+1 -> k=c+4, so adj and
// factor loads are contiguous int2/float2.
// lsum accumulates the POST-tf32-rounded P values -> numerator and denominator
// see identical weights (exact softmax of logits perturbed by <=1.2e-4).
// ---------------------------------------------------------------------------
#define SBS     68                              // smem row stride (floats)
#define BUFF    (2 * 64 * SBS)                  // hi+lo per buffer (floats)
#define SMEM_ATTN (2 * BUFF * 4)                // 69632 bytes

__global__ void __launch_bounds__(256, 2)
k_attn(const int* __restrict__ adj, float* __restrict__ out) {
    extern __shared__ __align__(16) float sB[];

    int tid  = threadIdx.x;
    int lane = tid & 31;
    int w    = tid >> 5;
    int b    = blockIdx.x >> 6;                 // 64 blocks per batch
    int i0   = (blockIdx.x & 63) * TMR;
    int rb   = (w >> 1) * 16;                   // row band within CTA
    int fh   = (w & 1) * 32;                    // feat half
    int r    = lane >> 2;                       // 0..7 (row-in-band & n-index)
    int c    = lane & 3;                        // k-quad index

    int grow = b * NN + i0 + rb + r;            // global row (and +8)
    float eA0 = g_eA[grow],     eC0 = g_eC[grow];
    float eA1 = g_eA[grow + 8], eC1 = g_eC[grow + 8];

    const int*   adj0 = adj + (size_t)grow * NN;
    const int*   adj1 = adj0 + (size_t)8 * NN;
    const float* eBp  = g_eB + b * NN;
    const float* eDp  = g_eD + b * NN;
    const float* gW   = g_Wh + (size_t)b * NN * FOUT;

    float acc[4][4];
#pragma unroll
    for (int nb = 0; nb < 4; nb++)
#pragma unroll
        for (int q = 0; q < 4; q++) acc[nb][q] = 0.f;
    float ls0 = 0.f, ls1 = 0.f;

    // B-conversion mapping: thread -> (tile-local j, 16-feat group)
    int cj   = tid & 63;
    int cf0  = (tid >> 6) << 4;
    int ccol = (cj & ~7) | ((cj >> 1) & 3) | ((cj & 1) << 2);   // pi(j)

    // Prologue: convert tile 0 into buffer 0
    {
#pragma unroll
        for (int u = 0; u < 4; u++) {
            float4 v = *(const float4*)(gW + (size_t)cj * FOUT + cf0 + 4 * u);
            float vv[4] = {v.x, v.y, v.z, v.w};
#pragma unroll
            for (int e = 0; e < 4; e++) {
                int f = cf0 + 4 * u + e;
                uint32_t hi = tf32_of(vv[e]);
                float lo = vv[e] - __uint_as_float(hi);
                sB[f * SBS + ccol]            = __uint_as_float(hi);
                sB[64 * SBS + f * SBS + ccol] = __uint_as_float(tf32_of(lo));
            }
        }
    }
    __syncthreads();

    int pb = 0;
    for (int t = 0; t < NT; t++) {
        int j0 = t * TJ;

        // Prefetch conversion loads for tile t+1 (clamped at the end)
        float4 cv[4];
        {
            int jn = (t + 1 < NT) ? (j0 + TJ + cj) : cj;
#pragma unroll
            for (int u = 0; u < 4; u++)
                cv[u] = *(const float4*)(gW + (size_t)jn * FOUT + cf0 + 4 * u);
        }

        const float* bufh = sB + pb * BUFF;
        const float* bufl = bufh + 64 * SBS;

#pragma unroll
        for (int kb = 0; kb < 8; kb++) {
            int jb = j0 + kb * 8 + 2 * c;
            int2   aA = *(const int2*)  (adj0 + jb);
            int2   aB = *(const int2*)  (adj1 + jb);
            float2 vB = *(const float2*)(eBp + jb);
            float2 vD = *(const float2*)(eDp + jb);

            float pA0 = (aA.x > 0) ? fmaxf(eA0 * vB.x, eC0 * vD.x) : 0.f;
            float pA1 = (aA.y > 0) ? fmaxf(eA0 * vB.y, eC0 * vD.y) : 0.f;
            float pB0 = (aB.x > 0) ? fmaxf(eA1 * vB.x, eC1 * vD.x) : 0.f;
            float pB1 = (aB.y > 0) ? fmaxf(eA1 * vB.y, eC1 * vD.y) : 0.f;

            uint32_t a0 = tf32_of(pA0);   // (row r,   k=c)
            uint32_t a1 = tf32_of(pB0);   // (row r+8, k=c)
            uint32_t a2 = tf32_of(pA1);   // (row r,   k=c+4)
            uint32_t a3 = tf32_of(pB1);   // (row r+8, k=c+4)
            ls0 += __uint_as_float(a0) + __uint_as_float(a2);
            ls1 += __uint_as_float(a1) + __uint_as_float(a3);

#pragma unroll
            for (int nb = 0; nb < 4; nb++) {
                int nrow = fh + nb * 8 + r;
                int kidx = kb * 8 + c;
                uint32_t b0h = __float_as_uint(bufh[nrow * SBS + kidx]);
                uint32_t b1h = __float_as_uint(bufh[nrow * SBS + kidx + 4]);
                uint32_t b0l = __float_as_uint(bufl[nrow * SBS + kidx]);
                uint32_t b1l = __float_as_uint(bufl[nrow * SBS + kidx + 4]);
                mma_tf32(acc[nb][0], acc[nb][1], acc[nb][2], acc[nb][3],
                         a0, a1, a2, a3, b0h, b1h);
                mma_tf32(acc[nb][0], acc[nb][1], acc[nb][2], acc[nb][3],
                         a0, a1, a2, a3, b0l, b1l);
            }
        }

        // Store conversion of tile t+1 into the other buffer
        {
            float* dh = sB + (1 - pb) * BUFF;
            float* dl = dh + 64 * SBS;
#pragma unroll
            for (int u = 0; u < 4; u++) {
                float vv[4] = {cv[u].x, cv[u].y, cv[u].z, cv[u].w};
#pragma unroll
                for (int e = 0; e < 4; e++) {
                    int f = cf0 + 4 * u + e;
                    uint32_t hi = tf32_of(vv[e]);
                    float lo = vv[e] - __uint_as_float(hi);
                    dh[f * SBS + ccol] = __uint_as_float(hi);
                    dl[f * SBS + ccol] = __uint_as_float(tf32_of(lo));
                }
            }
        }
        __syncthreads();
        pb ^= 1;
    }

    // Row-sum reduction within each k-quad (deterministic shuffle tree)
    ls0 += __shfl_xor_sync(0xFFFFFFFFu, ls0, 1);
    ls0 += __shfl_xor_sync(0xFFFFFFFFu, ls0, 2);
    ls1 += __shfl_xor_sync(0xFFFFFFFFu, ls1, 1);
    ls1 += __shfl_xor_sync(0xFFFFFFFFu, ls1, 2);

    // Epilogue: softmax divide, ELU, store (C-frag layout: cols 2c, 2c+1)
    float inv0 = 1.0f / ls0;
    float inv1 = 1.0f / ls1;
    float* o0 = out + (size_t)grow * FOUT;
    float* o1 = out + (size_t)(grow + 8) * FOUT;
#pragma unroll
    for (int nb = 0; nb < 4; nb++) {
        int col = fh + nb * 8 + 2 * c;
        float x0 = acc[nb][0] * inv0, x1 = acc[nb][1] * inv0;
        float x2 = acc[nb][2] * inv1, x3 = acc[nb][3] * inv1;
        float2 oA, oB;
        oA.x = (x0 > 0.f) ? x0 : expm1f(x0);
        oA.y = (x1 > 0.f) ? x1 : expm1f(x1);
        oB.x = (x2 > 0.f) ? x2 : expm1f(x2);
        oB.y = (x3 > 0.f) ? x3 : expm1f(x3);
        *(float2*)(o0 + col) = oA;
        *(float2*)(o1 + col) = oB;
    }
}

// ---------------------------------------------------------------------------
// Inputs (metadata order): h[f32], adj[i32], W[f32], a[f32], bias[f32]
// ---------------------------------------------------------------------------
extern "C" void kernel_launch(void* const* d_in, const int* in_sizes, int n_in,
                              void* d_out, int out_size) {
    const float* h    = (const float*)d_in[0];
    const int*   adj  = (const int*)  d_in[1];
    const float* W    = (const float*)d_in[2];
    const float* a    = (const float*)d_in[3];
    const float* bias = (const float*)d_in[4];
    float* out = (float*)d_out;

    cudaFuncSetAttribute(k_attn, cudaFuncAttributeMaxDynamicSharedMemorySize,
                         (int)SMEM_ATTN);

    k_init<<<1, 32>>>();
    k_proj<<<(BB * NN) / 64, 256>>>(h, W, a, bias);
    k_prep<<<(BB * NN) / 256, 256>>>();
    k_attn<<<BB * (NN / TMR), 256, SMEM_ATTN>>>(adj, out);
}

// round 6
// speedup vs baseline: 1.6987x; 1.2913x over previous
#include <cuda_runtime.h>
#include <cstdint>
#include <cstddef>

// Problem constants (fixed by the reference)
#define BB    4
#define NN    4096
#define FIN   256
#define FOUT  64
#define ALPHA 0.2f
#define NT    64              // j-tiles of 64

using u64 = unsigned long long;

// Scratch (device globals: no allocation allowed)
__device__ float g_Wh [BB * NN * FOUT];     // 4 MB, [b*N + j][f]
__device__ float g_Wh1[BB * NN];
__device__ float g_Wh2[BB * NN];
__device__ float g_max2[BB];
__device__ float g_eA[BB * NN];             // exp(w1 - m_i)
__device__ float g_eC[BB * NN];             // exp(a*w1 - m_i)
__device__ float g_eB[BB * NN];             // exp(w2)
__device__ float g_eD[BB * NN];             // exp(a*w2)
// Packed fragment-ready B: per (b,t): 1024 units x 16B = 16KB (4096 floats)
__device__ float g_Bpk[BB * NT * 4096];     // 4 MB

// ---------- packed f32x2 helpers (k_proj) ----------
__device__ __forceinline__ u64 pk2(float lo, float hi) {
    u64 r; asm("mov.b64 %0, {%1, %2};" : "=l"(r) : "f"(lo), "f"(hi)); return r;
}
__device__ __forceinline__ u64 fma2(u64 a, u64 b, u64 c) {
    u64 d; asm("fma.rn.f32x2 %0, %1, %2, %3;" : "=l"(d) : "l"(a), "l"(b), "l"(c)); return d;
}
__device__ __forceinline__ float2 upk2(u64 v) {
    float2 r; asm("mov.b64 {%0, %1}, %2;" : "=f"(r.x), "=f"(r.y) : "l"(v)); return r;
}

// bf16x2 pack: bits[31:16]=bf16(hi), bits[15:0]=bf16(lo)
__device__ __forceinline__ uint32_t cvt2(float hi, float lo) {
    uint32_t r; asm("cvt.rn.bf16x2.f32 %0, %1, %2;" : "=r"(r) : "f"(hi), "f"(lo)); return r;
}

// m16n8k16 bf16 MMA (baseline sm_80 ISA — compiles at compute_100)
__device__ __forceinline__ void mma_bf16(float* d, uint32_t a0, uint32_t a1,
                                         uint32_t a2, uint32_t a3,
                                         uint32_t b0, uint32_t b1) {
    asm volatile(
        "mma.sync.aligned.m16n8k16.row.col.f32.bf16.bf16.f32 "
        "{%0,%1,%2,%3}, {%4,%5,%6,%7}, {%8,%9}, {%0,%1,%2,%3};"
        : "+f"(d[0]), "+f"(d[1]), "+f"(d[2]), "+f"(d[3])
        : "r"(a0), "r"(a1), "r"(a2), "r"(a3), "r"(b0), "r"(b1));
}

__device__ __forceinline__ void cp16(uint32_t saddr, const void* g) {
    asm volatile("cp.async.cg.shared.global [%0], [%1], 16;"
                 :: "r"(saddr), "l"(g) : "memory");
}

// Order-independent (deterministic) float atomic max.
__device__ __forceinline__ void atomicMaxFloat(float* addr, float v) {
    if (v >= 0.f) atomicMax((int*)addr,          __float_as_int(v));
    else          atomicMin((unsigned int*)addr, __float_as_uint(v));
}

// ---------------------------------------------------------------------------
// K_init
// ---------------------------------------------------------------------------
__global__ void k_init() {
    if (threadIdx.x < BB) g_max2[threadIdx.x] = -3.0e38f;
}

// ---------------------------------------------------------------------------
// K_proj: tiled GEMM  Wh = h @ W + bias, fused Wh1/Wh2 dots + per-batch max.
// ---------------------------------------------------------------------------
__global__ void __launch_bounds__(256, 2)
k_proj(const float* __restrict__ h, const float* __restrict__ W,
       const float* __restrict__ a, const float* __restrict__ bias) {
    __shared__ __align__(16) float sH[64 * 68];
    __shared__ __align__(16) float sW[64 * 64];

    int tid = threadIdx.x;
    int ti = tid >> 4;
    int jq = tid & 15;
    int i0 = blockIdx.x * 64;

    u64 acc[4][2];
#pragma unroll
    for (int r = 0; r < 4; r++) { acc[r][0] = 0ull; acc[r][1] = 0ull; }

    for (int kc = 0; kc < 4; kc++) {
        int k0 = kc * 64;
#pragma unroll
        for (int u = 0; u < 4; u++) {
            int q = tid + u * 256;
            int row = q >> 4, c4 = q & 15;
            *(float4*)(sH + row * 68 + c4 * 4) =
                *(const float4*)(h + (size_t)(i0 + row) * FIN + k0 + c4 * 4);
            *(float4*)(sW + row * 64 + c4 * 4) =
                *(const float4*)(W + (size_t)(k0 + row) * FOUT + c4 * 4);
        }
        __syncthreads();

#pragma unroll 4
        for (int k = 0; k < 64; k++) {
            ulonglong2 wv = *(const ulonglong2*)(sW + k * 64 + 4 * jq);
#pragma unroll
            for (int r = 0; r < 4; r++) {
                float hv = sH[(ti * 4 + r) * 68 + k];
                u64 hh = pk2(hv, hv);
                acc[r][0] = fma2(hh, wv.x, acc[r][0]);
                acc[r][1] = fma2(hh, wv.y, acc[r][1]);
            }
        }
        __syncthreads();
    }

    float4 bv = *(const float4*)(bias + 4 * jq);
    float4 a1 = *(const float4*)(a + 4 * jq);
    float4 a2 = *(const float4*)(a + FOUT + 4 * jq);
    float p1[4], p2[4];
#pragma unroll
    for (int r = 0; r < 4; r++) {
        float2 v01 = upk2(acc[r][0]), v23 = upk2(acc[r][1]);
        float4 wh = make_float4(v01.x + bv.x, v01.y + bv.y,
                                v23.x + bv.z, v23.y + bv.w);
        int grow = i0 + ti * 4 + r;
        *(float4*)(g_Wh + (size_t)grow * FOUT + 4 * jq) = wh;
        p1[r] = wh.x * a1.x + wh.y * a1.y + wh.z * a1.z + wh.w * a1.w;
        p2[r] = wh.x * a2.x + wh.y * a2.y + wh.z * a2.z + wh.w * a2.w;
    }

    float* sR1 = sH;
    float* sR2 = sH + 1024;
#pragma unroll
    for (int r = 0; r < 4; r++) {
        sR1[jq * 64 + ti * 4 + r] = p1[r];
        sR2[jq * 64 + ti * 4 + r] = p2[r];
    }
    __syncthreads();
    if (tid < 64) {
        float w1 = 0.f, w2 = 0.f;
#pragma unroll
        for (int q = 0; q < 16; q++) {
            w1 += sR1[q * 64 + tid];
            w2 += sR2[q * 64 + tid];
        }
        g_Wh1[i0 + tid] = w1;
        g_Wh2[i0 + tid] = w2;
        float m = w2;
#pragma unroll
        for (int o = 16; o > 0; o >>= 1)
            m = fmaxf(m, __shfl_xor_sync(0xFFFFFFFFu, m, o));
        if ((tid & 31) == 0) atomicMaxFloat(&g_max2[i0 >> 12], m);
    }
}

// ---------------------------------------------------------------------------
// K_prep: factored attention exponential:
//   exp(lrelu(w1+w2) - m) = max(e^{w1-m} e^{w2}, e^{a w1 - m} e^{a w2})
// ---------------------------------------------------------------------------
__global__ void k_prep() {
    int idx = blockIdx.x * blockDim.x + threadIdx.x;
    if (idx >= BB * NN) return;
    int b = idx >> 12;
    float mx = g_max2[b];
    float w1 = g_Wh1[idx];
    float w2 = g_Wh2[idx];
    float e = w1 + mx;
    float m = fmaxf(e, ALPHA * e);
    g_eA[idx] = __expf(w1 - m);
    g_eC[idx] = __expf(ALPHA * w1 - m);
    g_eB[idx] = __expf(w2);
    g_eD[idx] = __expf(ALPHA * w2);
}

// ---------------------------------------------------------------------------
// K_pack: one-time bf16 hi/lo fragment packing of Wh for the PV MMA.
// j<->k permutation inside each kb16 block: j_local = 4c+m maps to
//   m=0 -> k=2c, m=1 -> k=2c+1, m=2 -> k=2c+8, m=3 -> k=2c+9.
// Unit (16B) at [b][t][kb16][f][c] = {Bh(2c,2c+1), Bh(2c+8,2c+9),
//                                     Bl(2c,2c+1), Bl(2c+8,2c+9)}.
// ---------------------------------------------------------------------------
__global__ void k_pack() {
    int idx = blockIdx.x * blockDim.x + threadIdx.x;   // 262144 units
    int f    = idx & 63;
    int c    = (idx >> 6) & 3;
    int kb   = (idx >> 8) & 3;
    int t    = (idx >> 10) & 63;
    int b    = idx >> 16;

    int j0 = t * 64 + kb * 16 + 4 * c;
    const float* src = g_Wh + (size_t)(b * NN + j0) * FOUT + f;
    float v0 = src[0];
    float v1 = src[FOUT];
    float v2 = src[2 * FOUT];
    float v3 = src[3 * FOUT];

    uint32_t h01 = cvt2(v1, v0);          // low = k=2c, high = k=2c+1
    uint32_t h23 = cvt2(v3, v2);          // low = k=2c+8, high = k=2c+9
    float l0 = v0 - __uint_as_float(h01 << 16);
    float l1 = v1 - __uint_as_float(h01 & 0xFFFF0000u);
    float l2 = v2 - __uint_as_float(h23 << 16);
    float l3 = v3 - __uint_as_float(h23 & 0xFFFF0000u);
    uint32_t lo01 = cvt2(l1, l0);
    uint32_t lo23 = cvt2(l3, l2);

    size_t u = ((size_t)(b * NT + t) * 1024) + (size_t)(kb * 256 + f * 4 + c);
    *(uint4*)(g_Bpk + u * 4) = make_uint4(h01, h23, lo01, lo23);
}

// ---------------------------------------------------------------------------
// A-fragment builder: one row's 4 j's -> masked factored softmax weights,
// bf16 hi/lo packed pairs. ls accumulates the (pre-split) p values; the
// hi+lo representation matches p to ~4e-6, keeping softmax consistent.
// ---------------------------------------------------------------------------
struct AF { uint32_t ha, hb, la, lb; };
__device__ __forceinline__ AF build_row(float eA, float eC, int4 A,
                                        float4 vB, float4 vD, float& ls) {
    float p0 = (A.x > 0) ? fmaxf(eA * vB.x, eC * vD.x) : 0.f;
    float p1 = (A.y > 0) ? fmaxf(eA * vB.y, eC * vD.y) : 0.f;
    float p2 = (A.z > 0) ? fmaxf(eA * vB.z, eC * vD.z) : 0.f;
    float p3 = (A.w > 0) ? fmaxf(eA * vB.w, eC * vD.w) : 0.f;
    ls += (p0 + p1) + (p2 + p3);
    AF o;
    o.ha = cvt2(p1, p0);
    o.hb = cvt2(p3, p2);
    float l0 = p0 - __uint_as_float(o.ha << 16);
    float l1 = p1 - __uint_as_float(o.ha & 0xFFFF0000u);
    float l2 = p2 - __uint_as_float(o.hb << 16);
    float l3 = p3 - __uint_as_float(o.hb & 0xFFFF0000u);
    o.la = cvt2(l1, l0);
    o.lb = cvt2(l3, l2);
    return o;
}

// ---------------------------------------------------------------------------
// K_attn: fused masked-softmax attention; PV on m16n8k16 bf16 (3-pass hi/lo).
// CTA: 128 thr / 4 warps / 64 rows. Warp w: rows (w>>1)*32+[0,32) as two m16
// bands, feats (w&1)*32+[0,32) as 4 n8 blocks. B streams from g_Bpk via
// cp.async into a 3-stage smem ring; zero conversion work in-loop.
// ---------------------------------------------------------------------------
__global__ void __launch_bounds__(128, 4)
k_attn(const int* __restrict__ adj, float* __restrict__ out) {
    __shared__ __align__(16) float sB[3 * 4096];   // 48 KB ring
    uint32_t sb = (uint32_t)__cvta_generic_to_shared(sB);

    int tid  = threadIdx.x;
    int lane = tid & 31;
    int w    = tid >> 5;
    int b    = blockIdx.x >> 6;                 // 64 blocks per batch
    int i0   = (blockIdx.x & 63) * 64;
    int rh   = (w >> 1) * 32;                   // row half
    int fh   = (w & 1) * 32;                    // feat half
    int r    = lane >> 2;                       // 0..7
    int c    = lane & 3;                        // 0..3

    int row0 = b * NN + i0 + rh + r;
    float eA0 = g_eA[row0],      eC0 = g_eC[row0];
    float eA1 = g_eA[row0 + 8],  eC1 = g_eC[row0 + 8];
    float eA2 = g_eA[row0 + 16], eC2 = g_eC[row0 + 16];
    float eA3 = g_eA[row0 + 24], eC3 = g_eC[row0 + 24];

    const int*   ap  = adj + (size_t)row0 * NN;
    const float* eBp = g_eB + b * NN;
    const float* eDp = g_eD + b * NN;
    const float* gB  = g_Bpk + (size_t)(b * NT) * 4096;

    float acc[2][4][4];
#pragma unroll
    for (int bd = 0; bd < 2; bd++)
#pragma unroll
        for (int nb = 0; nb < 4; nb++)
#pragma unroll
            for (int q = 0; q < 4; q++) acc[bd][nb][q] = 0.f;
    float ls[4] = {0.f, 0.f, 0.f, 0.f};

    // Prologue: stage tiles 0 and 1
#pragma unroll
    for (int i = 0; i < 8; i++)
        cp16(sb + (tid + i * 128) * 16, gB + (size_t)(tid + i * 128) * 4);
    asm volatile("cp.async.commit_group;" ::: "memory");
#pragma unroll
    for (int i = 0; i < 8; i++)
        cp16(sb + 16384 + (tid + i * 128) * 16,
             gB + 4096 + (size_t)(tid + i * 128) * 4);
    asm volatile("cp.async.commit_group;" ::: "memory");

    for (int t = 0; t < NT; t++) {
        asm volatile("cp.async.wait_group 1;" ::: "memory");
        __syncthreads();

        // Stage tile t+2 into the buffer freed by compute(t-1)
        if (t + 2 < NT) {
            uint32_t sdst = sb + ((t + 2) % 3) * 16384;
            const float* gsrc = gB + (size_t)(t + 2) * 4096;
#pragma unroll
            for (int i = 0; i < 8; i++)
                cp16(sdst + (tid + i * 128) * 16, gsrc + (size_t)(tid + i * 128) * 4);
        }
        asm volatile("cp.async.commit_group;" ::: "memory");

        const float* buf = sB + (t % 3) * 4096;
        int jt = t * 64;

#pragma unroll
        for (int kb = 0; kb < 4; kb++) {            // kb16 blocks
            int jc = jt + kb * 16 + 4 * c;
            int4 A0 = *(const int4*)(ap + jc);
            int4 A1 = *(const int4*)(ap + (size_t)8  * NN + jc);
            int4 A2 = *(const int4*)(ap + (size_t)16 * NN + jc);
            int4 A3 = *(const int4*)(ap + (size_t)24 * NN + jc);
            float4 vB = *(const float4*)(eBp + jc);
            float4 vD = *(const float4*)(eDp + jc);

            AF f0 = build_row(eA0, eC0, A0, vB, vD, ls[0]);
            AF f1 = build_row(eA1, eC1, A1, vB, vD, ls[1]);
            AF f2 = build_row(eA2, eC2, A2, vB, vD, ls[2]);
            AF f3 = build_row(eA3, eC3, A3, vB, vD, ls[3]);

            const float* bp = buf + kb * 1024 + c * 4;
#pragma unroll
            for (int nb = 0; nb < 4; nb++) {
                float4 u = *(const float4*)(bp + (fh + nb * 8 + r) * 16);
                uint32_t Bh0 = __float_as_uint(u.x), Bh1 = __float_as_uint(u.y);
                uint32_t Bl0 = __float_as_uint(u.z), Bl1 = __float_as_uint(u.w);
                // band 0 (rows r, r+8): hi*hi, hi*lo, lo*hi
                mma_bf16(acc[0][nb], f0.ha, f1.ha, f0.hb, f1.hb, Bh0, Bh1);
                mma_bf16(acc[0][nb], f0.ha, f1.ha, f0.hb, f1.hb, Bl0, Bl1);
                mma_bf16(acc[0][nb], f0.la, f1.la, f0.lb, f1.lb, Bh0, Bh1);
                // band 1 (rows r+16, r+24)
                mma_bf16(acc[1][nb], f2.ha, f3.ha, f2.hb, f3.hb, Bh0, Bh1);
                mma_bf16(acc[1][nb], f2.ha, f3.ha, f2.hb, f3.hb, Bl0, Bl1);
                mma_bf16(acc[1][nb], f2.la, f3.la, f2.lb, f3.lb, Bh0, Bh1);
            }
        }
    }

    // Deterministic row-sum reduce within each k-quad
#pragma unroll
    for (int q = 0; q < 4; q++) {
        ls[q] += __shfl_xor_sync(0xFFFFFFFFu, ls[q], 1);
        ls[q] += __shfl_xor_sync(0xFFFFFFFFu, ls[q], 2);
    }

    // Epilogue: softmax divide, ELU, store
#pragma unroll
    for (int bd = 0; bd < 2; bd++) {
        float inv0 = 1.0f / ls[bd * 2];
        float inv1 = 1.0f / ls[bd * 2 + 1];
        float* o0 = out + (size_t)(row0 + bd * 16) * FOUT;
        float* o1 = out + (size_t)(row0 + bd * 16 + 8) * FOUT;
#pragma unroll
        for (int nb = 0; nb < 4; nb++) {
            int col = fh + nb * 8 + 2 * c;
            float x0 = acc[bd][nb][0] * inv0, x1 = acc[bd][nb][1] * inv0;
            float x2 = acc[bd][nb][2] * inv1, x3 = acc[bd][nb][3] * inv1;
            float2 oA, oB;
            oA.x = (x0 > 0.f) ? x0 : expm1f(x0);
            oA.y = (x1 > 0.f) ? x1 : expm1f(x1);
            oB.x = (x2 > 0.f) ? x2 : expm1f(x2);
            oB.y = (x3 > 0.f) ? x3 : expm1f(x3);
            *(float2*)(o0 + col) = oA;
            *(float2*)(o1 + col) = oB;
        }
    }
}

// ---------------------------------------------------------------------------
// Inputs (metadata order): h[f32], adj[i32], W[f32], a[f32], bias[f32]
// ---------------------------------------------------------------------------
extern "C" void kernel_launch(void* const* d_in, const int* in_sizes, int n_in,
                              void* d_out, int out_size) {
    const float* h    = (const float*)d_in[0];
    const int*   adj  = (const int*)  d_in[1];
    const float* W    = (const float*)d_in[2];
    const float* a    = (const float*)d_in[3];
    const float* bias = (const float*)d_in[4];
    float* out = (float*)d_out;

    k_init<<<1, 32>>>();
    k_proj<<<(BB * NN) / 64, 256>>>(h, W, a, bias);
    k_prep<<<(BB * NN) / 256, 256>>>();
    k_pack<<<1024, 256>>>();
    k_attn<<<BB * (NN / 64), 128>>>(adj, out);
}

// round 7
// speedup vs baseline: 2.2178x; 1.3056x over previous
#include <cuda_runtime.h>
#include <cstdint>
#include <cstddef>

// Problem constants (fixed by the reference)
#define BB    4
#define NN    4096
#define FIN   256
#define FOUT  64
#define ALPHA 0.2f
#define NT    64              // j-tiles of 64

using u64 = unsigned long long;

// Scratch (device globals: no allocation allowed)
__device__ float g_Wh [BB * NN * FOUT];     // 4 MB, [b*N + j][f]
__device__ float g_Wh1[BB * NN];
__device__ float g_Wh2[BB * NN];
__device__ float g_max2[BB];
__device__ float g_eA[BB * NN];             // exp(w1 - m_i)
__device__ float g_eC[BB * NN];             // exp(a*w1 - m_i)
__device__ float g_eB[BB * NN];             // exp(w2)
__device__ float g_eD[BB * NN];             // exp(a*w2)
// Packed fragment-ready B: per (b,t): 1024 units x 16B = 16KB (4096 floats)
__device__ float g_Bpk[BB * NT * 4096];     // 4 MB

// ---------- packed f32x2 helpers (k_proj) ----------
__device__ __forceinline__ u64 pk2(float lo, float hi) {
    u64 r; asm("mov.b64 %0, {%1, %2};" : "=l"(r) : "f"(lo), "f"(hi)); return r;
}
__device__ __forceinline__ u64 fma2(u64 a, u64 b, u64 c) {
    u64 d; asm("fma.rn.f32x2 %0, %1, %2, %3;" : "=l"(d) : "l"(a), "l"(b), "l"(c)); return d;
}
__device__ __forceinline__ float2 upk2(u64 v) {
    float2 r; asm("mov.b64 {%0, %1}, %2;" : "=f"(r.x), "=f"(r.y) : "l"(v)); return r;
}

// bf16x2 pack: bits[31:16]=bf16(hi), bits[15:0]=bf16(lo)
__device__ __forceinline__ uint32_t cvt2(float hi, float lo) {
    uint32_t r; asm("cvt.rn.bf16x2.f32 %0, %1, %2;" : "=r"(r) : "f"(hi), "f"(lo)); return r;
}

// m16n8k16 bf16 MMA (baseline sm_80 ISA — compiles at compute_100)
__device__ __forceinline__ void mma_bf16(float* d, uint32_t a0, uint32_t a1,
                                         uint32_t a2, uint32_t a3,
                                         uint32_t b0, uint32_t b1) {
    asm volatile(
        "mma.sync.aligned.m16n8k16.row.col.f32.bf16.bf16.f32 "
        "{%0,%1,%2,%3}, {%4,%5,%6,%7}, {%8,%9}, {%0,%1,%2,%3};"
        : "+f"(d[0]), "+f"(d[1]), "+f"(d[2]), "+f"(d[3])
        : "r"(a0), "r"(a1), "r"(a2), "r"(a3), "r"(b0), "r"(b1));
}

__device__ __forceinline__ void cp16(uint32_t saddr, const void* g) {
    asm volatile("cp.async.cg.shared.global [%0], [%1], 16;"
                 :: "r"(saddr), "l"(g) : "memory");
}

// Order-independent (deterministic) float atomic max.
__device__ __forceinline__ void atomicMaxFloat(float* addr, float v) {
    if (v >= 0.f) atomicMax((int*)addr,          __float_as_int(v));
    else          atomicMin((unsigned int*)addr, __float_as_uint(v));
}

// ---------------------------------------------------------------------------
// K_init
// ---------------------------------------------------------------------------
__global__ void k_init() {
    if (threadIdx.x < BB) g_max2[threadIdx.x] = -3.0e38f;
}

// ---------------------------------------------------------------------------
// K_proj: tiled GEMM  Wh = h @ W + bias, fused Wh1/Wh2 dots + per-batch max.
// ---------------------------------------------------------------------------
__global__ void __launch_bounds__(256, 2)
k_proj(const float* __restrict__ h, const float* __restrict__ W,
       const float* __restrict__ a, const float* __restrict__ bias) {
    __shared__ __align__(16) float sH[64 * 68];
    __shared__ __align__(16) float sW[64 * 64];

    int tid = threadIdx.x;
    int ti = tid >> 4;
    int jq = tid & 15;
    int i0 = blockIdx.x * 64;

    u64 acc[4][2];
#pragma unroll
    for (int r = 0; r < 4; r++) { acc[r][0] = 0ull; acc[r][1] = 0ull; }

    for (int kc = 0; kc < 4; kc++) {
        int k0 = kc * 64;
#pragma unroll
        for (int u = 0; u < 4; u++) {
            int q = tid + u * 256;
            int row = q >> 4, c4 = q & 15;
            *(float4*)(sH + row * 68 + c4 * 4) =
                *(const float4*)(h + (size_t)(i0 + row) * FIN + k0 + c4 * 4);
            *(float4*)(sW + row * 64 + c4 * 4) =
                *(const float4*)(W + (size_t)(k0 + row) * FOUT + c4 * 4);
        }
        __syncthreads();

#pragma unroll 4
        for (int k = 0; k < 64; k++) {
            ulonglong2 wv = *(const ulonglong2*)(sW + k * 64 + 4 * jq);
#pragma unroll
            for (int r = 0; r < 4; r++) {
                float hv = sH[(ti * 4 + r) * 68 + k];
                u64 hh = pk2(hv, hv);
                acc[r][0] = fma2(hh, wv.x, acc[r][0]);
                acc[r][1] = fma2(hh, wv.y, acc[r][1]);
            }
        }
        __syncthreads();
    }

    float4 bv = *(const float4*)(bias + 4 * jq);
    float4 a1 = *(const float4*)(a + 4 * jq);
    float4 a2 = *(const float4*)(a + FOUT + 4 * jq);
    float p1[4], p2[4];
#pragma unroll
    for (int r = 0; r < 4; r++) {
        float2 v01 = upk2(acc[r][0]), v23 = upk2(acc[r][1]);
        float4 wh = make_float4(v01.x + bv.x, v01.y + bv.y,
                                v23.x + bv.z, v23.y + bv.w);
        int grow = i0 + ti * 4 + r;
        *(float4*)(g_Wh + (size_t)grow * FOUT + 4 * jq) = wh;
        p1[r] = wh.x * a1.x + wh.y * a1.y + wh.z * a1.z + wh.w * a1.w;
        p2[r] = wh.x * a2.x + wh.y * a2.y + wh.z * a2.z + wh.w * a2.w;
    }

    float* sR1 = sH;
    float* sR2 = sH + 1024;
#pragma unroll
    for (int r = 0; r < 4; r++) {
        sR1[jq * 64 + ti * 4 + r] = p1[r];
        sR2[jq * 64 + ti * 4 + r] = p2[r];
    }
    __syncthreads();
    if (tid < 64) {
        float w1 = 0.f, w2 = 0.f;
#pragma unroll
        for (int q = 0; q < 16; q++) {
            w1 += sR1[q * 64 + tid];
            w2 += sR2[q * 64 + tid];
        }
        g_Wh1[i0 + tid] = w1;
        g_Wh2[i0 + tid] = w2;
        float m = w2;
#pragma unroll
        for (int o = 16; o > 0; o >>= 1)
            m = fmaxf(m, __shfl_xor_sync(0xFFFFFFFFu, m, o));
        if ((tid & 31) == 0) atomicMaxFloat(&g_max2[i0 >> 12], m);
    }
}

// ---------------------------------------------------------------------------
// K_prep_pack: (a) factored attention exponentials for the first 16384
// threads; (b) one-time bf16 hi/lo fragment packing of Wh for all 262144
// pack units. Merged so the launch group is 4 kernels (ncu lands on k_attn).
//
// Pack unit (16B) at [b][t][kb16][f][c] = {Bh(2c,2c+1), Bh(2c+8,2c+9),
//                                          Bl(2c,2c+1), Bl(2c+8,2c+9)}
// with j-permutation: j_local = 4c+m -> k: m0->2c, m1->2c+1, m2->2c+8, m3->2c+9.
// ---------------------------------------------------------------------------
__global__ void k_prep_pack() {
    int idx = blockIdx.x * blockDim.x + threadIdx.x;   // 262144

    if (idx < BB * NN) {
        int b = idx >> 12;
        float mx = g_max2[b];
        float w1 = g_Wh1[idx];
        float w2 = g_Wh2[idx];
        float e = w1 + mx;
        float m = fmaxf(e, ALPHA * e);     // m_i >= all e_ij
        g_eA[idx] = __expf(w1 - m);
        g_eC[idx] = __expf(ALPHA * w1 - m);
        g_eB[idx] = __expf(w2);
        g_eD[idx] = __expf(ALPHA * w2);
    }

    int f    = idx & 63;
    int c    = (idx >> 6) & 3;
    int kb   = (idx >> 8) & 3;
    int t    = (idx >> 10) & 63;
    int b    = idx >> 16;

    int j0 = t * 64 + kb * 16 + 4 * c;
    const float* src = g_Wh + (size_t)(b * NN + j0) * FOUT + f;
    float v0 = src[0];
    float v1 = src[FOUT];
    float v2 = src[2 * FOUT];
    float v3 = src[3 * FOUT];

    uint32_t h01 = cvt2(v1, v0);          // k=2c, 2c+1
    uint32_t h23 = cvt2(v3, v2);          // k=2c+8, 2c+9
    float l0 = v0 - __uint_as_float(h01 << 16);
    float l1 = v1 - __uint_as_float(h01 & 0xFFFF0000u);
    float l2 = v2 - __uint_as_float(h23 << 16);
    float l3 = v3 - __uint_as_float(h23 & 0xFFFF0000u);
    uint32_t lo01 = cvt2(l1, l0);
    uint32_t lo23 = cvt2(l3, l2);

    size_t u = ((size_t)(b * NT + t) * 1024) + (size_t)(kb * 256 + f * 4 + c);
    *(uint4*)(g_Bpk + u * 4) = make_uint4(h01, h23, lo01, lo23);
}

// ---------------------------------------------------------------------------
// A-fragment builder: one row's 4 j's -> masked factored softmax weights,
// bf16 hi/lo packed pairs. ls accumulates the (pre-split) p values.
// ---------------------------------------------------------------------------
struct AF { uint32_t ha, hb, la, lb; };
__device__ __forceinline__ AF build_row(float eA, float eC, int4 A,
                                        float4 vB, float4 vD, float& ls) {
    float p0 = (A.x > 0) ? fmaxf(eA * vB.x, eC * vD.x) : 0.f;
    float p1 = (A.y > 0) ? fmaxf(eA * vB.y, eC * vD.y) : 0.f;
    float p2 = (A.z > 0) ? fmaxf(eA * vB.z, eC * vD.z) : 0.f;
    float p3 = (A.w > 0) ? fmaxf(eA * vB.w, eC * vD.w) : 0.f;
    ls += (p0 + p1) + (p2 + p3);
    AF o;
    o.ha = cvt2(p1, p0);
    o.hb = cvt2(p3, p2);
    float l0 = p0 - __uint_as_float(o.ha << 16);
    float l1 = p1 - __uint_as_float(o.ha & 0xFFFF0000u);
    float l2 = p2 - __uint_as_float(o.hb << 16);
    float l3 = p3 - __uint_as_float(o.hb & 0xFFFF0000u);
    o.la = cvt2(l1, l0);
    o.lb = cvt2(l3, l2);
    return o;
}

// ---------------------------------------------------------------------------
// K_attn: fused masked-softmax attention; PV on m16n8k16 bf16 (3-pass hi/lo).
// CTA: 128 thr / 4 warps / 64 rows. Warp w owns rows w*16..w*16+15 (one m16
// band) x ALL 64 feats (8 n8-blocks) -> A-build and adjacency loads are done
// exactly once per row (no cross-warp duplication). B streams from g_Bpk via
// cp.async into a 3-stage smem ring; zero conversion work in-loop.
// ---------------------------------------------------------------------------
__global__ void __launch_bounds__(128, 4)
k_attn(const int* __restrict__ adj, float* __restrict__ out) {
    __shared__ __align__(16) float sB[3 * 4096];   // 48 KB ring
    uint32_t sb = (uint32_t)__cvta_generic_to_shared(sB);

    int tid  = threadIdx.x;
    int lane = tid & 31;
    int w    = tid >> 5;
    int b    = blockIdx.x >> 6;                 // 64 blocks per batch
    int i0   = (blockIdx.x & 63) * 64;
    int r    = lane >> 2;                       // 0..7
    int c    = lane & 3;                        // 0..3

    int row0 = b * NN + i0 + w * 16 + r;        // global row (and +8)
    float eA0 = g_eA[row0],     eC0 = g_eC[row0];
    float eA1 = g_eA[row0 + 8], eC1 = g_eC[row0 + 8];

    const int*   ap  = adj + (size_t)row0 * NN;
    const float* eBp = g_eB + b * NN;
    const float* eDp = g_eD + b * NN;
    const float* gB  = g_Bpk + (size_t)(b * NT) * 4096;

    float acc[8][4];
#pragma unroll
    for (int nb = 0; nb < 8; nb++)
#pragma unroll
        for (int q = 0; q < 4; q++) acc[nb][q] = 0.f;
    float ls0 = 0.f, ls1 = 0.f;

    // Prologue: stage tiles 0 and 1
#pragma unroll
    for (int i = 0; i < 8; i++)
        cp16(sb + (tid + i * 128) * 16, gB + (size_t)(tid + i * 128) * 4);
    asm volatile("cp.async.commit_group;" ::: "memory");
#pragma unroll
    for (int i = 0; i < 8; i++)
        cp16(sb + 16384 + (tid + i * 128) * 16,
             gB + 4096 + (size_t)(tid + i * 128) * 4);
    asm volatile("cp.async.commit_group;" ::: "memory");

    for (int t = 0; t < NT; t++) {
        asm volatile("cp.async.wait_group 1;" ::: "memory");
        __syncthreads();

        // Stage tile t+2 into the buffer freed by compute(t-1)
        if (t + 2 < NT) {
            uint32_t sdst = sb + ((t + 2) % 3) * 16384;
            const float* gsrc = gB + (size_t)(t + 2) * 4096;
#pragma unroll
            for (int i = 0; i < 8; i++)
                cp16(sdst + (tid + i * 128) * 16, gsrc + (size_t)(tid + i * 128) * 4);
        }
        asm volatile("cp.async.commit_group;" ::: "memory");

        const float* buf = sB + (t % 3) * 4096;
        int jt = t * 64;

#pragma unroll
        for (int kb = 0; kb < 4; kb++) {            // kb16 blocks
            int jc = jt + kb * 16 + 4 * c;
            int4 A0 = *(const int4*)(ap + jc);
            int4 A1 = *(const int4*)(ap + (size_t)8 * NN + jc);
            float4 vB = *(const float4*)(eBp + jc);
            float4 vD = *(const float4*)(eDp + jc);

            AF f0 = build_row(eA0, eC0, A0, vB, vD, ls0);
            AF f1 = build_row(eA1, eC1, A1, vB, vD, ls1);

            const float* bp = buf + kb * 1024 + c * 4;
#pragma unroll
            for (int nb = 0; nb < 8; nb++) {
                float4 u = *(const float4*)(bp + (nb * 8 + r) * 16);
                uint32_t Bh0 = __float_as_uint(u.x), Bh1 = __float_as_uint(u.y);
                uint32_t Bl0 = __float_as_uint(u.z), Bl1 = __float_as_uint(u.w);
                mma_bf16(acc[nb], f0.ha, f1.ha, f0.hb, f1.hb, Bh0, Bh1);
                mma_bf16(acc[nb], f0.ha, f1.ha, f0.hb, f1.hb, Bl0, Bl1);
                mma_bf16(acc[nb], f0.la, f1.la, f0.lb, f1.lb, Bh0, Bh1);
            }
        }
    }

    // Deterministic row-sum reduce within each k-quad (warp-local rows)
    ls0 += __shfl_xor_sync(0xFFFFFFFFu, ls0, 1);
    ls0 += __shfl_xor_sync(0xFFFFFFFFu, ls0, 2);
    ls1 += __shfl_xor_sync(0xFFFFFFFFu, ls1, 1);
    ls1 += __shfl_xor_sync(0xFFFFFFFFu, ls1, 2);

    // Epilogue: softmax divide, ELU, store
    float inv0 = 1.0f / ls0;
    float inv1 = 1.0f / ls1;
    float* o0 = out + (size_t)row0 * FOUT;
    float* o1 = out + (size_t)(row0 + 8) * FOUT;
#pragma unroll
    for (int nb = 0; nb < 8; nb++) {
        int col = nb * 8 + 2 * c;
        float x0 = acc[nb][0] * inv0, x1 = acc[nb][1] * inv0;
        float x2 = acc[nb][2] * inv1, x3 = acc[nb][3] * inv1;
        float2 oA, oB;
        oA.x = (x0 > 0.f) ? x0 : expm1f(x0);
        oA.y = (x1 > 0.f) ? x1 : expm1f(x1);
        oB.x = (x2 > 0.f) ? x2 : expm1f(x2);
        oB.y = (x3 > 0.f) ? x3 : expm1f(x3);
        *(float2*)(o0 + col) = oA;
        *(float2*)(o1 + col) = oB;
    }
}

// ---------------------------------------------------------------------------
// Inputs (metadata order): h[f32], adj[i32], W[f32], a[f32], bias[f32]
// Launch group is 4 kernels: ncu (-s 5, P=2 pre-launches) captures index 3
// = k_attn.
// ---------------------------------------------------------------------------
extern "C" void kernel_launch(void* const* d_in, const int* in_sizes, int n_in,
                              void* d_out, int out_size) {
    const float* h    = (const float*)d_in[0];
    const int*   adj  = (const int*)  d_in[1];
    const float* W    = (const float*)d_in[2];
    const float* a    = (const float*)d_in[3];
    const float* bias = (const float*)d_in[4];
    float* out = (float*)d_out;

    k_init<<<1, 32>>>();
    k_proj<<<(BB * NN) / 64, 256>>>(h, W, a, bias);
    k_prep_pack<<<1024, 256>>>();
    k_attn<<<BB * (NN / 64), 128>>>(adj, out);
}